// round 1
// baseline (speedup 1.0000x reference)
#include <cuda_runtime.h>
#include <math.h>

#define S_LEN   16384
#define HIDDEN  1280
#define NH      16
#define HD      80
#define WIN     64
#define NW      256            // 16384 / 64
#define QKV_N   3840
#define SCALE   0.11180339887498949f   // 80^-0.5

// Scratch (device-global: allocation-free rule)
__device__ float g_qkv[(size_t)S_LEN * QKV_N];     // 252 MB
__device__ float g_attn[(size_t)S_LEN * HIDDEN];   // 84 MB

// ---------------------------------------------------------------------------
// SGEMM: C[M,N] = A[M,K] @ B[K,N] + bias[N]
// BM=BN=128, BK=8, 256 threads, 8x8 register tile, double-buffered smem.
// All dims divisible by tile sizes for this problem (no bounds checks).
// ---------------------------------------------------------------------------
__global__ __launch_bounds__(256) void sgemm_bias_kernel(
    const float* __restrict__ A, const float* __restrict__ B,
    const float* __restrict__ bias, float* __restrict__ C,
    int M, int N, int K)
{
    const int BM = 128, BN = 128, BK = 8;
    __shared__ float As[2][BK][BM];
    __shared__ float Bs[2][BK][BN];

    const int tid  = threadIdx.x;
    const int row0 = blockIdx.y * BM;
    const int col0 = blockIdx.x * BN;

    // global->smem load mapping (one float4 each per tile)
    const int aRow = tid >> 1;            // 0..127
    const int aCol = (tid & 1) << 2;      // 0 or 4
    const int bRow = tid >> 5;            // 0..7
    const int bCol = (tid & 31) << 2;     // 0..124

    const float* Aptr = A + (size_t)(row0 + aRow) * K + aCol;
    const float* Bptr = B + (size_t)bRow * N + col0 + bCol;

    float4 aReg = *(const float4*)(Aptr);
    float4 bReg = *(const float4*)(Bptr);
    As[0][aCol + 0][aRow] = aReg.x;
    As[0][aCol + 1][aRow] = aReg.y;
    As[0][aCol + 2][aRow] = aReg.z;
    As[0][aCol + 3][aRow] = aReg.w;
    *(float4*)&Bs[0][bRow][bCol] = bReg;
    __syncthreads();

    const int ty = tid >> 4;   // 0..15 -> rows ty*8..ty*8+7
    const int tx = tid & 15;   // 0..15 -> cols tx*8..tx*8+7

    float acc[8][8];
    #pragma unroll
    for (int i = 0; i < 8; i++)
        #pragma unroll
        for (int j = 0; j < 8; j++) acc[i][j] = 0.0f;

    const int kTiles = K / BK;
    int buf = 0;
    for (int t = 0; t < kTiles; ++t) {
        if (t + 1 < kTiles) {
            aReg = *(const float4*)(Aptr + (size_t)(t + 1) * BK);
            bReg = *(const float4*)(Bptr + (size_t)(t + 1) * BK * N);
        }
        float ar[8], br[8];
        #pragma unroll
        for (int k = 0; k < BK; k++) {
            #pragma unroll
            for (int i = 0; i < 8; i++) ar[i] = As[buf][k][ty * 8 + i];
            #pragma unroll
            for (int j = 0; j < 8; j++) br[j] = Bs[buf][k][tx * 8 + j];
            #pragma unroll
            for (int i = 0; i < 8; i++)
                #pragma unroll
                for (int j = 0; j < 8; j++) acc[i][j] = fmaf(ar[i], br[j], acc[i][j]);
        }
        if (t + 1 < kTiles) {
            const int nb = buf ^ 1;
            As[nb][aCol + 0][aRow] = aReg.x;
            As[nb][aCol + 1][aRow] = aReg.y;
            As[nb][aCol + 2][aRow] = aReg.z;
            As[nb][aCol + 3][aRow] = aReg.w;
            *(float4*)&Bs[nb][bRow][bCol] = bReg;
            __syncthreads();
            buf = nb;
        }
    }

    // epilogue: bias + store
    #pragma unroll
    for (int i = 0; i < 8; i++) {
        const size_t r = (size_t)(row0 + ty * 8 + i);
        #pragma unroll
        for (int j = 0; j < 8; j += 4) {
            const int c = col0 + tx * 8 + j;
            float4 v;
            v.x = acc[i][j + 0] + bias[c + 0];
            v.y = acc[i][j + 1] + bias[c + 1];
            v.z = acc[i][j + 2] + bias[c + 2];
            v.w = acc[i][j + 3] + bias[c + 3];
            *(float4*)&C[r * N + c] = v;
        }
    }
}

// ---------------------------------------------------------------------------
// RoPE in-place on q and k halves of g_qkv.
// Each thread owns one (s, qk, h, d<40) pair -> writes cols d and d+40.
// ---------------------------------------------------------------------------
__global__ __launch_bounds__(256) void rope_kernel(
    const float* __restrict__ cosT, const float* __restrict__ sinT)
{
    int idx = blockIdx.x * 256 + threadIdx.x;   // [s][qk][h][d]
    const int d  = idx % 40; idx /= 40;
    const int h  = idx % NH; idx /= NH;
    const int qk = idx & 1;  idx >>= 1;
    const int s  = idx;
    if (s >= S_LEN) return;

    const size_t base = (size_t)s * QKV_N + qk * HIDDEN + h * HD + d;
    const float a  = g_qkv[base];
    const float b  = g_qkv[base + 40];
    const float c  = cosT[(size_t)s * HD + d];
    const float sn = sinT[(size_t)s * HD + d];
    g_qkv[base]      = a * c - b * sn;
    g_qkv[base + 40] = b * c + a * sn;
}

// ---------------------------------------------------------------------------
// Windowed attention: one CTA per (window, head). 128 threads.
// Dynamic smem: Qt[80][65] | KV union (Kt[80][65] / Vs[64][80]) | Ss[64][65]
// ---------------------------------------------------------------------------
#define QT_PITCH 65
#define SS_PITCH 65
#define SM_QT    0
#define SM_KV    (80 * QT_PITCH)            // 5200 floats
#define SM_SS    (2 * 80 * QT_PITCH)        // 10400 floats
#define ATTN_SMEM_FLOATS (2 * 80 * QT_PITCH + 64 * SS_PITCH)   // 14560
#define ATTN_SMEM_BYTES  (ATTN_SMEM_FLOATS * 4)                // 58240

__global__ __launch_bounds__(128) void attn_kernel()
{
    extern __shared__ float sm[];
    float* Qt = sm + SM_QT;   // [80][65] transposed
    float* Kt = sm + SM_KV;   // [80][65] transposed (later reused as Vs[64][80])
    float* Vs = sm + SM_KV;   // row-major [64][80]
    float* Ss = sm + SM_SS;   // [64][65]

    const int h   = blockIdx.x;     // head
    const int w   = blockIdx.y;     // window
    const int tid = threadIdx.x;    // 0..127

    // ---- load Q, K (transposed, padded) -------------------------------
    // 1280 float4 per tile; 10 per thread. idx -> t = idx/20, d0 = (idx%20)*4
    #pragma unroll
    for (int it = 0; it < 10; it++) {
        const int idx = tid + it * 128;
        const int t   = idx / 20;
        const int d0  = (idx % 20) * 4;
        const size_t rowBase = (size_t)(w * WIN + t) * QKV_N + h * HD + d0;
        float4 q4 = *(const float4*)&g_qkv[rowBase];
        float4 k4 = *(const float4*)&g_qkv[rowBase + HIDDEN];
        Qt[(d0 + 0) * QT_PITCH + t] = q4.x;
        Qt[(d0 + 1) * QT_PITCH + t] = q4.y;
        Qt[(d0 + 2) * QT_PITCH + t] = q4.z;
        Qt[(d0 + 3) * QT_PITCH + t] = q4.w;
        Kt[(d0 + 0) * QT_PITCH + t] = k4.x;
        Kt[(d0 + 1) * QT_PITCH + t] = k4.y;
        Kt[(d0 + 2) * QT_PITCH + t] = k4.z;
        Kt[(d0 + 3) * QT_PITCH + t] = k4.w;
    }
    __syncthreads();

    // ---- scores: S = scale * Q K^T  (each thread: 8 rows x 4 cols) ----
    {
        const int r0 = (tid >> 4) * 8;    // 8 groups of 8 rows
        const int c0 = (tid & 15) * 4;    // 16 groups of 4 cols
        float acc[8][4];
        #pragma unroll
        for (int i = 0; i < 8; i++)
            #pragma unroll
            for (int j = 0; j < 4; j++) acc[i][j] = 0.0f;

        for (int d = 0; d < HD; d++) {
            float ar[8], br[4];
            #pragma unroll
            for (int i = 0; i < 8; i++) ar[i] = Qt[d * QT_PITCH + r0 + i];
            #pragma unroll
            for (int j = 0; j < 4; j++) br[j] = Kt[d * QT_PITCH + c0 + j];
            #pragma unroll
            for (int i = 0; i < 8; i++)
                #pragma unroll
                for (int j = 0; j < 4; j++) acc[i][j] = fmaf(ar[i], br[j], acc[i][j]);
        }
        #pragma unroll
        for (int i = 0; i < 8; i++)
            #pragma unroll
            for (int j = 0; j < 4; j++)
                Ss[(r0 + i) * SS_PITCH + c0 + j] = acc[i][j] * SCALE;
    }
    __syncthreads();

    // ---- load V (row-major) -- overwrites Kt buffer -------------------
    #pragma unroll
    for (int it = 0; it < 10; it++) {
        const int idx = tid + it * 128;
        const int t   = idx / 20;
        const int d0  = (idx % 20) * 4;
        const size_t rowBase = (size_t)(w * WIN + t) * QKV_N + 2 * HIDDEN + h * HD + d0;
        *(float4*)&Vs[t * HD + d0] = *(const float4*)&g_qkv[rowBase];
    }

    // ---- softmax: warp per 16 rows, lane l handles cols l, l+32 -------
    {
        const int warp = tid >> 5;
        const int lane = tid & 31;
        for (int rr = 0; rr < 16; rr++) {
            const int r = warp * 16 + rr;
            float x0 = Ss[r * SS_PITCH + lane];
            float x1 = Ss[r * SS_PITCH + lane + 32];
            float m = fmaxf(x0, x1);
            #pragma unroll
            for (int o = 16; o > 0; o >>= 1)
                m = fmaxf(m, __shfl_xor_sync(0xffffffffu, m, o));
            float e0 = __expf(x0 - m);
            float e1 = __expf(x1 - m);
            float s = e0 + e1;
            #pragma unroll
            for (int o = 16; o > 0; o >>= 1)
                s += __shfl_xor_sync(0xffffffffu, s, o);
            const float inv = 1.0f / s;
            Ss[r * SS_PITCH + lane]      = e0 * inv;
            Ss[r * SS_PITCH + lane + 32] = e1 * inv;
        }
    }
    __syncthreads();

    // ---- out = W @ V  (each thread: 8 rows x 5 cols) ------------------
    {
        const int r0 = (tid >> 4) * 8;
        const int c0 = (tid & 15) * 5;
        float acc[8][5];
        #pragma unroll
        for (int i = 0; i < 8; i++)
            #pragma unroll
            for (int j = 0; j < 5; j++) acc[i][j] = 0.0f;

        for (int k = 0; k < WIN; k++) {
            float sr[8], vr[5];
            #pragma unroll
            for (int i = 0; i < 8; i++) sr[i] = Ss[(r0 + i) * SS_PITCH + k];
            #pragma unroll
            for (int j = 0; j < 5; j++) vr[j] = Vs[k * HD + c0 + j];
            #pragma unroll
            for (int i = 0; i < 8; i++)
                #pragma unroll
                for (int j = 0; j < 5; j++) acc[i][j] = fmaf(sr[i], vr[j], acc[i][j]);
        }
        #pragma unroll
        for (int i = 0; i < 8; i++) {
            const size_t outBase = (size_t)(w * WIN + r0 + i) * HIDDEN + h * HD + c0;
            #pragma unroll
            for (int j = 0; j < 5; j++)
                g_attn[outBase + j] = acc[i][j];
        }
    }
}

// ---------------------------------------------------------------------------
// Launch
// ---------------------------------------------------------------------------
extern "C" void kernel_launch(void* const* d_in, const int* in_sizes, int n_in,
                              void* d_out, int out_size)
{
    const float* x      = (const float*)d_in[0];
    const float* cosT   = (const float*)d_in[1];
    const float* sinT   = (const float*)d_in[2];
    // d_in[3] = cu_seqlens (uniform 64-token windows; constant by construction)
    const float* w_qkv  = (const float*)d_in[4];
    const float* b_qkv  = (const float*)d_in[5];
    const float* w_proj = (const float*)d_in[6];
    const float* b_proj = (const float*)d_in[7];
    float* out = (float*)d_out;

    float* qkv  = nullptr;
    float* attn = nullptr;
    cudaGetSymbolAddress((void**)&qkv,  g_qkv);
    cudaGetSymbolAddress((void**)&attn, g_attn);

    cudaFuncSetAttribute(attn_kernel,
                         cudaFuncAttributeMaxDynamicSharedMemorySize,
                         ATTN_SMEM_BYTES);

    // 1) QKV = x @ w_qkv + b_qkv
    {
        dim3 grid(QKV_N / 128, S_LEN / 128);
        sgemm_bias_kernel<<<grid, 256>>>(x, w_qkv, b_qkv, qkv,
                                         S_LEN, QKV_N, HIDDEN);
    }
    // 2) RoPE in place on q, k
    {
        const int total = S_LEN * 2 * NH * 40;   // 20,971,520
        rope_kernel<<<total / 256, 256>>>(cosT, sinT);
    }
    // 3) windowed attention
    {
        dim3 grid(NH, NW);
        attn_kernel<<<grid, 128, ATTN_SMEM_BYTES>>>();
    }
    // 4) out = attn @ w_proj + b_proj
    {
        dim3 grid(HIDDEN / 128, S_LEN / 128);
        sgemm_bias_kernel<<<grid, 256>>>(attn, w_proj, b_proj, out,
                                         S_LEN, HIDDEN, HIDDEN);
    }
}

// round 4
// speedup vs baseline: 2.7397x; 2.7397x over previous
#include <cuda_runtime.h>
#include <cuda_bf16.h>
#include <cstdint>
#include <math.h>

#define S_LEN   16384
#define HIDDEN  1280
#define NH      16
#define HD      80
#define WIN     64
#define NW      256
#define QKV_N   3840
#define K3      3840            // stacked split-K (3 * 1280)
#define NCHUNK  (K3 / 64)       // 60
#define SCALE   0.11180339887498949f

// ---------------- scratch (device globals: allocation-free rule) -----------
__device__ __align__(256) float         g_qkv [(size_t)S_LEN * QKV_N];
__device__ __align__(256) float         g_attn[(size_t)S_LEN * HIDDEN];
__device__ __align__(256) __nv_bfloat16 g_ax   [(size_t)S_LEN * K3];
__device__ __align__(256) __nv_bfloat16 g_aattn[(size_t)S_LEN * K3];
__device__ __align__(256) __nv_bfloat16 g_bqkv [(size_t)QKV_N * K3];
__device__ __align__(256) __nv_bfloat16 g_bproj[(size_t)HIDDEN * K3];

// ---------------- helpers ---------------------------------------------------
__device__ __forceinline__ uint32_t smem_u32(const void* p) {
    uint32_t a;
    asm("{ .reg .u64 t; cvta.to.shared.u64 t, %1; cvt.u32.u64 %0, t; }"
        : "=r"(a) : "l"(p));
    return a;
}
#define SWZ(x) ((x) ^ (((x) >> 3) & 0x70))

__device__ __forceinline__ void cp16(uint32_t s, const void* g) {
    asm volatile("cp.async.cg.shared.global [%0], [%1], 16;\n" :: "r"(s), "l"(g));
}
#define CP_COMMIT() asm volatile("cp.async.commit_group;" ::: "memory")
#define CP_WAIT0()  asm volatile("cp.async.wait_group 0;" ::: "memory")
#define CP_WAIT1()  asm volatile("cp.async.wait_group 1;" ::: "memory")

__device__ __forceinline__ void ldm_x4(uint32_t* r, uint32_t addr) {
    asm volatile("ldmatrix.sync.aligned.m8n8.x4.shared.b16 {%0,%1,%2,%3}, [%4];"
                 : "=r"(r[0]), "=r"(r[1]), "=r"(r[2]), "=r"(r[3]) : "r"(addr));
}
__device__ __forceinline__ void mma_bf16(float* c, const uint32_t* a,
                                         const uint32_t* b) {
    asm volatile("mma.sync.aligned.m16n8k16.row.col.f32.bf16.bf16.f32 "
                 "{%0,%1,%2,%3}, {%4,%5,%6,%7}, {%8,%9}, {%0,%1,%2,%3};"
                 : "+f"(c[0]), "+f"(c[1]), "+f"(c[2]), "+f"(c[3])
                 : "r"(a[0]), "r"(a[1]), "r"(a[2]), "r"(a[3]),
                   "r"(b[0]), "r"(b[1]));
}

// ---------------------------------------------------------------------------
// GEMM: C[M, Nt] = A'[M, K3] @ B'[Nt, K3]^T + bias
// Tile 128x128, BK=64 (128-byte rows, SW128 swizzle), 256 threads (8 warps),
// warp tile 32x64 via mma.sync m16n8k16 bf16, cp.async double buffer.
// ---------------------------------------------------------------------------
#define GEMM_SMEM_BYTES 65536   // A[2][16K] | B[2][16K]

__global__ __launch_bounds__(256) void gemm_mma_kernel(
    const __nv_bfloat16* __restrict__ A, const __nv_bfloat16* __restrict__ B,
    const float* __restrict__ bias, float* __restrict__ C, int Nt)
{
    extern __shared__ char sm[];
    const uint32_t sbase = smem_u32(sm);
    const uint32_t s_A = sbase;              // 2 x 16 KB
    const uint32_t s_B = sbase + 32768;      // 2 x 16 KB

    const int tid  = threadIdx.x;
    const int lane = tid & 31;
    const int warp = tid >> 5;
    const int wm   = warp >> 1;   // 0..3  -> rows wm*32
    const int wn   = warp & 1;    // 0..1  -> cols wn*64
    const int n0   = blockIdx.x * 128;
    const int m0   = blockIdx.y * 128;

    const char* Abase = (const char*)A + (size_t)m0 * (K3 * 2);
    const char* Bbase = (const char*)B + (size_t)n0 * (K3 * 2);

    // precomputed ldmatrix shared addresses (chunk-invariant parts)
    // A: row = wm*32 + mt*16 + (lane&15), unit = kstep*2 + (lane>>4)
    const int a_row  = wm * 32 + (lane & 15);
    const int a_unit = lane >> 4;
    // B: row = wn*64 + np*16 + 8*(lane>>4) + (lane&7), unit = kstep*2 + ((lane>>3)&1)
    const int b_row  = wn * 64 + 8 * (lane >> 4) + (lane & 7);
    const int b_unit = (lane >> 3) & 1;

    float acc[2][8][4];
    #pragma unroll
    for (int mt = 0; mt < 2; mt++)
        #pragma unroll
        for (int nt = 0; nt < 8; nt++)
            #pragma unroll
            for (int j = 0; j < 4; j++) acc[mt][nt][j] = 0.0f;

    // ---- loader for one 64-wide K chunk ----
    auto load_chunk = [&](int c, int buf) {
        const uint32_t aB = s_A + buf * 16384;
        const uint32_t bB = s_B + buf * 16384;
        const size_t koff = (size_t)c * 128;
        #pragma unroll
        for (int i = 0; i < 4; i++) {           // A: 1024 16B units
            const int u = tid + i * 256, row = u >> 3, cb = u & 7;
            cp16(aB + SWZ(row * 128 + cb * 16),
                 Abase + (size_t)row * (K3 * 2) + koff + cb * 16);
        }
        #pragma unroll
        for (int i = 0; i < 4; i++) {           // B: 1024 16B units
            const int u = tid + i * 256, row = u >> 3, cb = u & 7;
            cp16(bB + SWZ(row * 128 + cb * 16),
                 Bbase + (size_t)row * (K3 * 2) + koff + cb * 16);
        }
        CP_COMMIT();
    };

    load_chunk(0, 0);

    for (int c = 0; c < NCHUNK; ++c) {
        const int buf = c & 1;
        if (c + 1 < NCHUNK) { load_chunk(c + 1, buf ^ 1); CP_WAIT1(); }
        else                { CP_WAIT0(); }
        __syncthreads();

        const uint32_t aB = s_A + buf * 16384;
        const uint32_t bB = s_B + buf * 16384;

        #pragma unroll
        for (int ks = 0; ks < 4; ks++) {
            uint32_t afr[2][4];
            #pragma unroll
            for (int mt = 0; mt < 2; mt++) {
                const int row = a_row + mt * 16;
                const int kk  = ks * 2 + a_unit;
                ldm_x4(afr[mt], aB + SWZ(row * 128 + kk * 16));
            }
            uint32_t bfr[4][4];
            #pragma unroll
            for (int np = 0; np < 4; np++) {
                const int row = b_row + np * 16;
                const int kk  = ks * 2 + b_unit;
                ldm_x4(bfr[np], bB + SWZ(row * 128 + kk * 16));
            }
            #pragma unroll
            for (int mt = 0; mt < 2; mt++)
                #pragma unroll
                for (int nt = 0; nt < 8; nt++)
                    mma_bf16(acc[mt][nt], afr[mt], &bfr[nt >> 1][(nt & 1) * 2]);
        }
        __syncthreads();   // buffer reuse protection
    }

    // ---- epilogue: bias + direct stores -----------------------------------
    #pragma unroll
    for (int mt = 0; mt < 2; mt++) {
        const int r0 = m0 + wm * 32 + mt * 16 + (lane >> 2);
        #pragma unroll
        for (int nt = 0; nt < 8; nt++) {
            const int cc = n0 + wn * 64 + nt * 8 + 2 * (lane & 3);
            const float b0 = bias[cc], b1 = bias[cc + 1];
            float2 v0 = {acc[mt][nt][0] + b0, acc[mt][nt][1] + b1};
            float2 v1 = {acc[mt][nt][2] + b0, acc[mt][nt][3] + b1};
            *(float2*)&C[(size_t)r0 * Nt + cc]       = v0;
            *(float2*)&C[(size_t)(r0 + 8) * Nt + cc] = v1;
        }
    }
}

// ---------------------------------------------------------------------------
// split fp32 [M, 1280] -> bf16 [M, 3840] stacked [hi | hi | lo]
// ---------------------------------------------------------------------------
__global__ __launch_bounds__(256) void split_kernel(
    const float* __restrict__ in, __nv_bfloat16* __restrict__ out, int total4)
{
    const int i = blockIdx.x * 256 + threadIdx.x;
    if (i >= total4) return;
    const int row = i / (HIDDEN / 4);
    const int c4  = (i % (HIDDEN / 4)) * 4;
    const float4 v = *(const float4*)(in + (size_t)row * HIDDEN + c4);
    __nv_bfloat16 h[4], l[4];
    const float vv[4] = {v.x, v.y, v.z, v.w};
    #pragma unroll
    for (int j = 0; j < 4; j++) {
        h[j] = __float2bfloat16(vv[j]);
        l[j] = __float2bfloat16(vv[j] - __bfloat162float(h[j]));
    }
    ushort4 hp = {__bfloat16_as_ushort(h[0]), __bfloat16_as_ushort(h[1]),
                  __bfloat16_as_ushort(h[2]), __bfloat16_as_ushort(h[3])};
    ushort4 lp = {__bfloat16_as_ushort(l[0]), __bfloat16_as_ushort(l[1]),
                  __bfloat16_as_ushort(l[2]), __bfloat16_as_ushort(l[3])};
    __nv_bfloat16* o = out + (size_t)row * K3 + c4;
    *(ushort4*)(o)              = hp;
    *(ushort4*)(o + HIDDEN)     = hp;
    *(ushort4*)(o + 2 * HIDDEN) = lp;
}

// ---------------------------------------------------------------------------
// transpose + split: w [1280, N] fp32 -> out [N, 3840] bf16 [hi | lo | hi]
// (matches A stacking [hi | hi | lo]: AhBh + AhBl + AlBh)
// ---------------------------------------------------------------------------
__global__ void wsplit_kernel(const float* __restrict__ w,
                              __nv_bfloat16* __restrict__ out, int N)
{
    __shared__ float t[32][33];
    const int n0 = blockIdx.x * 32;
    const int k0 = blockIdx.y * 32;
    const int tx = threadIdx.x, ty = threadIdx.y;   // block (32, 8)
    #pragma unroll
    for (int j = 0; j < 4; j++)
        t[ty + j * 8][tx] = w[(size_t)(k0 + ty + j * 8) * N + n0 + tx];
    __syncthreads();
    #pragma unroll
    for (int j = 0; j < 4; j++) {
        const int r = ty + j * 8;                   // n-local
        const float v = t[tx][r];
        const __nv_bfloat16 h = __float2bfloat16(v);
        const __nv_bfloat16 l = __float2bfloat16(v - __bfloat162float(h));
        __nv_bfloat16* o = out + (size_t)(n0 + r) * K3 + k0 + tx;
        o[0]          = h;
        o[HIDDEN]     = l;
        o[2 * HIDDEN] = h;
    }
}

// ---------------------------------------------------------------------------
// RoPE in-place on q, k halves of g_qkv
// ---------------------------------------------------------------------------
__global__ __launch_bounds__(256) void rope_kernel(
    const float* __restrict__ cosT, const float* __restrict__ sinT)
{
    int idx = blockIdx.x * 256 + threadIdx.x;
    const int d  = idx % 40; idx /= 40;
    const int h  = idx % NH; idx /= NH;
    const int qk = idx & 1;  idx >>= 1;
    const int s  = idx;
    if (s >= S_LEN) return;
    const size_t base = (size_t)s * QKV_N + qk * HIDDEN + h * HD + d;
    const float a  = g_qkv[base];
    const float b  = g_qkv[base + 40];
    const float c  = cosT[(size_t)s * HD + d];
    const float sn = sinT[(size_t)s * HD + d];
    g_qkv[base]      = a * c - b * sn;
    g_qkv[base + 40] = b * c + a * sn;
}

// ---------------------------------------------------------------------------
// Windowed attention: one CTA per (window, head)
// ---------------------------------------------------------------------------
#define QT_PITCH 65
#define SS_PITCH 65
#define SM_KV    (80 * QT_PITCH)
#define SM_SS    (2 * 80 * QT_PITCH)
#define ATTN_SMEM_BYTES ((2 * 80 * QT_PITCH + 64 * SS_PITCH) * 4)

__global__ __launch_bounds__(128) void attn_kernel()
{
    extern __shared__ float smf[];
    float* Qt = smf;
    float* Kt = smf + SM_KV;
    float* Vs = smf + SM_KV;
    float* Ss = smf + SM_SS;

    const int h   = blockIdx.x;
    const int w   = blockIdx.y;
    const int tid = threadIdx.x;

    #pragma unroll
    for (int it = 0; it < 10; it++) {
        const int idx = tid + it * 128;
        const int t   = idx / 20;
        const int d0  = (idx % 20) * 4;
        const size_t rowBase = (size_t)(w * WIN + t) * QKV_N + h * HD + d0;
        float4 q4 = *(const float4*)&g_qkv[rowBase];
        float4 k4 = *(const float4*)&g_qkv[rowBase + HIDDEN];
        Qt[(d0 + 0) * QT_PITCH + t] = q4.x;
        Qt[(d0 + 1) * QT_PITCH + t] = q4.y;
        Qt[(d0 + 2) * QT_PITCH + t] = q4.z;
        Qt[(d0 + 3) * QT_PITCH + t] = q4.w;
        Kt[(d0 + 0) * QT_PITCH + t] = k4.x;
        Kt[(d0 + 1) * QT_PITCH + t] = k4.y;
        Kt[(d0 + 2) * QT_PITCH + t] = k4.z;
        Kt[(d0 + 3) * QT_PITCH + t] = k4.w;
    }
    __syncthreads();

    {
        const int r0 = (tid >> 4) * 8;
        const int c0 = (tid & 15) * 4;
        float acc[8][4];
        #pragma unroll
        for (int i = 0; i < 8; i++)
            #pragma unroll
            for (int j = 0; j < 4; j++) acc[i][j] = 0.0f;
        for (int d = 0; d < HD; d++) {
            float ar[8], br[4];
            #pragma unroll
            for (int i = 0; i < 8; i++) ar[i] = Qt[d * QT_PITCH + r0 + i];
            #pragma unroll
            for (int j = 0; j < 4; j++) br[j] = Kt[d * QT_PITCH + c0 + j];
            #pragma unroll
            for (int i = 0; i < 8; i++)
                #pragma unroll
                for (int j = 0; j < 4; j++) acc[i][j] = fmaf(ar[i], br[j], acc[i][j]);
        }
        #pragma unroll
        for (int i = 0; i < 8; i++)
            #pragma unroll
            for (int j = 0; j < 4; j++)
                Ss[(r0 + i) * SS_PITCH + c0 + j] = acc[i][j] * SCALE;
    }
    __syncthreads();

    #pragma unroll
    for (int it = 0; it < 10; it++) {
        const int idx = tid + it * 128;
        const int t   = idx / 20;
        const int d0  = (idx % 20) * 4;
        const size_t rowBase = (size_t)(w * WIN + t) * QKV_N + 2 * HIDDEN + h * HD + d0;
        *(float4*)&Vs[t * HD + d0] = *(const float4*)&g_qkv[rowBase];
    }

    {
        const int warp = tid >> 5;
        const int lane = tid & 31;
        for (int rr = 0; rr < 16; rr++) {
            const int r = warp * 16 + rr;
            float x0 = Ss[r * SS_PITCH + lane];
            float x1 = Ss[r * SS_PITCH + lane + 32];
            float m = fmaxf(x0, x1);
            #pragma unroll
            for (int o = 16; o > 0; o >>= 1)
                m = fmaxf(m, __shfl_xor_sync(0xffffffffu, m, o));
            float e0 = __expf(x0 - m);
            float e1 = __expf(x1 - m);
            float s = e0 + e1;
            #pragma unroll
            for (int o = 16; o > 0; o >>= 1)
                s += __shfl_xor_sync(0xffffffffu, s, o);
            const float inv = 1.0f / s;
            Ss[r * SS_PITCH + lane]      = e0 * inv;
            Ss[r * SS_PITCH + lane + 32] = e1 * inv;
        }
    }
    __syncthreads();

    {
        const int r0 = (tid >> 4) * 8;
        const int c0 = (tid & 15) * 5;
        float acc[8][5];
        #pragma unroll
        for (int i = 0; i < 8; i++)
            #pragma unroll
            for (int j = 0; j < 5; j++) acc[i][j] = 0.0f;
        for (int k = 0; k < WIN; k++) {
            float sr[8], vr[5];
            #pragma unroll
            for (int i = 0; i < 8; i++) sr[i] = Ss[(r0 + i) * SS_PITCH + k];
            #pragma unroll
            for (int j = 0; j < 5; j++) vr[j] = Vs[k * HD + c0 + j];
            #pragma unroll
            for (int i = 0; i < 8; i++)
                #pragma unroll
                for (int j = 0; j < 5; j++) acc[i][j] = fmaf(sr[i], vr[j], acc[i][j]);
        }
        #pragma unroll
        for (int i = 0; i < 8; i++) {
            const size_t outBase = (size_t)(w * WIN + r0 + i) * HIDDEN + h * HD + c0;
            #pragma unroll
            for (int j = 0; j < 5; j++)
                g_attn[outBase + j] = acc[i][j];
        }
    }
}

// ---------------------------------------------------------------------------
// Launch
// ---------------------------------------------------------------------------
extern "C" void kernel_launch(void* const* d_in, const int* in_sizes, int n_in,
                              void* d_out, int out_size)
{
    const float* x      = (const float*)d_in[0];
    const float* cosT   = (const float*)d_in[1];
    const float* sinT   = (const float*)d_in[2];
    const float* w_qkv  = (const float*)d_in[4];
    const float* b_qkv  = (const float*)d_in[5];
    const float* w_proj = (const float*)d_in[6];
    const float* b_proj = (const float*)d_in[7];
    float* out = (float*)d_out;

    float *qkv, *attn;
    __nv_bfloat16 *ax, *aattn, *bqkv, *bproj;
    cudaGetSymbolAddress((void**)&qkv,   g_qkv);
    cudaGetSymbolAddress((void**)&attn,  g_attn);
    cudaGetSymbolAddress((void**)&ax,    g_ax);
    cudaGetSymbolAddress((void**)&aattn, g_aattn);
    cudaGetSymbolAddress((void**)&bqkv,  g_bqkv);
    cudaGetSymbolAddress((void**)&bproj, g_bproj);

    cudaFuncSetAttribute(gemm_mma_kernel,
                         cudaFuncAttributeMaxDynamicSharedMemorySize,
                         GEMM_SMEM_BYTES);
    cudaFuncSetAttribute(attn_kernel,
                         cudaFuncAttributeMaxDynamicSharedMemorySize,
                         ATTN_SMEM_BYTES);

    const int total4 = S_LEN * HIDDEN / 4;

    // 1) split x -> A'
    split_kernel<<<(total4 + 255) / 256, 256>>>(x, ax, total4);
    // 2) transpose+split weights
    {
        dim3 blk(32, 8);
        wsplit_kernel<<<dim3(QKV_N / 32, HIDDEN / 32), blk>>>(w_qkv, bqkv, QKV_N);
        wsplit_kernel<<<dim3(HIDDEN / 32, HIDDEN / 32), blk>>>(w_proj, bproj, HIDDEN);
    }
    // 3) QKV = A' B'^T + bias  (tensor core, mma.sync)
    gemm_mma_kernel<<<dim3(QKV_N / 128, S_LEN / 128), 256, GEMM_SMEM_BYTES>>>(
        ax, bqkv, b_qkv, qkv, QKV_N);
    // 4) RoPE
    rope_kernel<<<(S_LEN * 2 * NH * 40) / 256, 256>>>(cosT, sinT);
    // 5) windowed attention
    attn_kernel<<<dim3(NH, NW), 128, ATTN_SMEM_BYTES>>>();
    // 6) split attn -> A'
    split_kernel<<<(total4 + 255) / 256, 256>>>(attn, aattn, total4);
    // 7) out = A' B'^T + bias  (tensor core, mma.sync)
    gemm_mma_kernel<<<dim3(HIDDEN / 128, S_LEN / 128), 256, GEMM_SMEM_BYTES>>>(
        aattn, bproj, b_proj, out, HIDDEN);
}